// round 15
// baseline (speedup 1.0000x reference)
#include <cuda_runtime.h>
#include <cuda_bf16.h>
#include <cstdint>

// Problem constants
#define NUM_CITIES 50000
#define EMB 50
#define EMBP 52          // padded to multiple of 4
#define HID 64
#define G4 256           // 4*HID
#define BATCH 1024
#define SEQ 512
#define BR 4             // batch rows per LSTM block
#define NT 256           // threads per block
#define NPB 782          // (NUM_CITIES+63)/64 logits col-blocks

typedef unsigned long long ull;

// ---------------- scratch (static __device__ globals; no allocation) ----------
__device__ __align__(16) float g_ht[HID * BATCH];        // final hidden, transposed [k][m]
__device__ __align__(16) float g_Wt[HID * NUM_CITIES];   // W_fc transposed [k][n]
__device__ __align__(16) float g_Wih[G4 * EMBP];         // W_ih zero-padded rows (16B aligned)
__device__ float g_partial[(size_t)BATCH * NPB];         // per-(row, colblock) exp sums
__device__ float g_inv[BATCH];                           // 1 / rowsum(exp(logits))

// ---------------- packed f32x2 helpers ---------------------------------------
__device__ __forceinline__ ull pack2(float x, float y) {
    ull r; asm("mov.b64 %0, {%1, %2};" : "=l"(r) : "f"(x), "f"(y)); return r;
}
__device__ __forceinline__ ull fma2(ull a, ull b, ull c) {
    ull d; asm("fma.rn.f32x2 %0, %1, %2, %3;" : "=l"(d) : "l"(a), "l"(b), "l"(c)); return d;
}
__device__ __forceinline__ float2 unpack2(ull v) {
    float2 f; asm("mov.b64 {%0, %1}, %2;" : "=f"(f.x), "=f"(f.y) : "l"(v)); return f;
}
__device__ __forceinline__ float sig_f(float v) {
    return __fdividef(1.0f, 1.0f + __expf(-v));
}
// fast tanh: 1 - 2/(e^{2|x|}+1), sign restored; saturates to +/-1 on overflow
__device__ __forceinline__ float tanh_f(float v) {
    float a = fabsf(v);
    float e = __expf(2.0f * a);
    float r = 1.0f - __fdividef(2.0f, e + 1.0f);
    return copysignf(r, v);
}

// ---------------- K0a: transpose W_fc [N,64] -> g_Wt [64,N] -------------------
__global__ void transpose_wfc_kernel(const float* __restrict__ W_fc) {
    __shared__ float t[32][33];
    int n0 = blockIdx.x * 32, k0 = blockIdx.y * 32;
    int n = n0 + threadIdx.y, k = k0 + threadIdx.x;
    if (n < NUM_CITIES) t[threadIdx.y][threadIdx.x] = W_fc[(size_t)n * HID + k];
    __syncthreads();
    int kk = k0 + threadIdx.y, nn = n0 + threadIdx.x;
    if (nn < NUM_CITIES) g_Wt[(size_t)kk * NUM_CITIES + nn] = t[threadIdx.x][threadIdx.y];
}

// ---------------- K0b: zero-pad W_ih rows to 52 (16B-aligned rows) ------------
__global__ void pad_wih_kernel(const float* __restrict__ W_ih) {
    int g = blockIdx.x, k = threadIdx.x;          // <<<256, EMBP>>>
    g_Wih[g * EMBP + k] = (k < EMB) ? W_ih[g * EMB + k] : 0.0f;
}

// ---------------- K1: fused embedding + LSTM ----------------------------------
// grid=256 (BR=4 rows/block), NT=256, 2 CTAs/SM. One thread per gate row g.
// k-split trick: accumulator lo half sums even-k terms, hi half odd-k terms;
// weight operand = two consecutive weights (plain 16B load, no duplication).
__global__ void __launch_bounds__(NT, 2) lstm_kernel(
    const int*   __restrict__ x,
    const float* __restrict__ emb,
    const float* __restrict__ W_hh,
    const float* __restrict__ b_ih,
    const float* __restrict__ b_hh)
{
    __shared__ __align__(16) float e_sh[2][BR][EMBP];   // double-buffered embeddings
    __shared__ __align__(16) float h_sh[BR][HID];
    __shared__ float c_sh[BR][HID];
    __shared__ float gates_sh[BR][G4];

    const int tid  = threadIdx.x;
    const int g    = tid;
    const int row0 = blockIdx.x * BR;

    // zero h, c  (BR*HID = 256 = NT: one element each)
    { int r = tid >> 6, j = tid & 63; h_sh[r][j] = 0.0f; c_sh[r][j] = 0.0f; }
    // zero e pads (2 bufs x 4 rows x 2 tail elems = 16)
    if (tid < 16) {
        int b = tid >> 3, rr = (tid >> 1) & 3, kk = EMB + (tid & 1);
        e_sh[b][rr][kk] = 0.0f;
    }

    // W_hh row for this gate in registers as 32 packed pairs (64 regs)
    ull whh2[32];
    {
        const ulonglong2* wh = (const ulonglong2*)(W_hh + g * HID);  // 256B-aligned rows
#pragma unroll
        for (int c = 0; c < 16; c++) { ulonglong2 v = wh[c]; whh2[2 * c] = v.x; whh2[2 * c + 1] = v.y; }
    }
    const float bias = b_ih[g] + b_hh[g];
    const float4* wih4 = (const float4*)(g_Wih + g * EMBP);          // 13 chunks, L1/L2-hot

    // embedding-prefetch role for threads 0..199
    const bool isld = tid < BR * EMB;
    const int  pr_raw = tid / EMB;
    const int  pr = (pr_raw < BR) ? pr_raw : (BR - 1);
    const int  pk = tid - pr_raw * EMB;
    const int* xrow = x + (size_t)(row0 + pr) * SEQ;

    if (isld) e_sh[0][pr][pk] = emb[(size_t)xrow[0] * EMB + pk];
    __syncthreads();

    const bool is_tanh = (g >= 2 * HID) && (g < 3 * HID);  // warp-uniform

    int cur = 0;
    for (int t = 0; t < SEQ; ++t) {
        // prefetch e(t+1) into a register (hidden behind the dot products)
        float pf = 0.0f;
        const bool haspf = isld && (t + 1 < SEQ);
        if (haspf) pf = emb[(size_t)xrow[t + 1] * EMB + pk];

        ull a0 = pack2(bias, 0.0f);
        ull a1 = a0, a2 = a0, a3 = a0;

        // input-side: 13 chunks of 4 k's
#pragma unroll
        for (int c = 0; c < 13; c++) {
            ulonglong2 w  = *(const ulonglong2*)(wih4 + c);
            ulonglong2 e0 = *(const ulonglong2*)&e_sh[cur][0][4 * c];
            ulonglong2 e1 = *(const ulonglong2*)&e_sh[cur][1][4 * c];
            ulonglong2 e2 = *(const ulonglong2*)&e_sh[cur][2][4 * c];
            ulonglong2 e3 = *(const ulonglong2*)&e_sh[cur][3][4 * c];
            a0 = fma2(e0.x, w.x, a0); a1 = fma2(e1.x, w.x, a1);
            a2 = fma2(e2.x, w.x, a2); a3 = fma2(e3.x, w.x, a3);
            a0 = fma2(e0.y, w.y, a0); a1 = fma2(e1.y, w.y, a1);
            a2 = fma2(e2.y, w.y, a2); a3 = fma2(e3.y, w.y, a3);
        }
        // hidden-side: 16 chunks of 4 k's, weights in registers
#pragma unroll
        for (int c = 0; c < 16; c++) {
            ulonglong2 h0 = *(const ulonglong2*)&h_sh[0][4 * c];
            ulonglong2 h1 = *(const ulonglong2*)&h_sh[1][4 * c];
            ulonglong2 h2 = *(const ulonglong2*)&h_sh[2][4 * c];
            ulonglong2 h3 = *(const ulonglong2*)&h_sh[3][4 * c];
            ull wA = whh2[2 * c], wB = whh2[2 * c + 1];
            a0 = fma2(h0.x, wA, a0); a1 = fma2(h1.x, wA, a1);
            a2 = fma2(h2.x, wA, a2); a3 = fma2(h3.x, wA, a3);
            a0 = fma2(h0.y, wB, a0); a1 = fma2(h1.y, wB, a1);
            a2 = fma2(h2.y, wB, a2); a3 = fma2(h3.y, wB, a3);
        }

        // fold halves + activation
        float2 f0 = unpack2(a0), f1 = unpack2(a1), f2 = unpack2(a2), f3 = unpack2(a3);
        float v0 = f0.x + f0.y, v1 = f1.x + f1.y, v2 = f2.x + f2.y, v3 = f3.x + f3.y;
        if (is_tanh) { v0 = tanh_f(v0); v1 = tanh_f(v1); v2 = tanh_f(v2); v3 = tanh_f(v3); }
        else         { v0 = sig_f(v0);  v1 = sig_f(v1);  v2 = sig_f(v2);  v3 = sig_f(v3);  }
        gates_sh[0][g] = v0; gates_sh[1][g] = v1; gates_sh[2][g] = v2; gates_sh[3][g] = v3;
        __syncthreads();

        // stash prefetched embedding into the other buffer
        if (haspf) e_sh[cur ^ 1][pr][pk] = pf;

        // c/h update: BR*HID = 256 tasks, one per thread
        {
            int r = tid >> 6, j = tid & 63;
            float iv = gates_sh[r][j];
            float fv = gates_sh[r][HID + j];
            float gv = gates_sh[r][2 * HID + j];
            float ov = gates_sh[r][3 * HID + j];
            float cc = fv * c_sh[r][j] + iv * gv;
            c_sh[r][j] = cc;
            h_sh[r][j] = ov * tanh_f(cc);
        }
        __syncthreads();
        cur ^= 1;
    }

    // final hidden, transposed for the GEMM: g_ht[j][m]
    {
        int r = tid >> 6, j = tid & 63;
        g_ht[(size_t)j * BATCH + row0 + r] = h_sh[r][j];
    }
}

// ---------------- K2: out = exp(h @ W_fc^T + b_fc), + per-block row sums ------
__global__ void __launch_bounds__(NT) logits_kernel(
    const float* __restrict__ b_fc, float* __restrict__ out)
{
    __shared__ __align__(16) float A_sh[HID][64];   // [k][m]
    __shared__ __align__(16) float B_sh[HID][64];   // [k][n]
    const int tid = threadIdx.x;
    const int m0 = blockIdx.y * 64;
    const int n0 = blockIdx.x * 64;

    for (int i = tid; i < 64 * 64; i += NT) {
        int k = i >> 6, m = i & 63;
        A_sh[k][m] = g_ht[(size_t)k * BATCH + m0 + m];
    }
    for (int i = tid; i < 64 * 64; i += NT) {
        int k = i >> 6, n = i & 63;
        int ngg = n0 + n;
        B_sh[k][n] = (ngg < NUM_CITIES) ? g_Wt[(size_t)k * NUM_CITIES + ngg] : 0.0f;
    }
    __syncthreads();

    const int tx = tid & 15;   // col group (4 cols)
    const int ty = tid >> 4;   // row group (4 rows = 2 packed pairs)

    ull acc[2][4];
#pragma unroll
    for (int p = 0; p < 2; p++)
#pragma unroll
        for (int c = 0; c < 4; c++) acc[p][c] = 0ull;

#pragma unroll 16
    for (int k = 0; k < HID; k++) {
        ulonglong2 a2 = *(const ulonglong2*)&A_sh[k][ty * 4];
        float4 b4 = *(const float4*)&B_sh[k][tx * 4];
        ull b0 = pack2(b4.x, b4.x), b1 = pack2(b4.y, b4.y);
        ull b2 = pack2(b4.z, b4.z), b3 = pack2(b4.w, b4.w);
        acc[0][0] = fma2(a2.x, b0, acc[0][0]);
        acc[1][0] = fma2(a2.y, b0, acc[1][0]);
        acc[0][1] = fma2(a2.x, b1, acc[0][1]);
        acc[1][1] = fma2(a2.y, b1, acc[1][1]);
        acc[0][2] = fma2(a2.x, b2, acc[0][2]);
        acc[1][2] = fma2(a2.y, b2, acc[1][2]);
        acc[0][3] = fma2(a2.x, b3, acc[0][3]);
        acc[1][3] = fma2(a2.y, b3, acc[1][3]);
    }

    int ng = n0 + tx * 4;
    float rs0 = 0.0f, rs1 = 0.0f, rs2 = 0.0f, rs3 = 0.0f;
    if (ng < NUM_CITIES) {     // NUM_CITIES % 4 == 0 -> float4 fully in-bounds
        float4 bv = *(const float4*)&b_fc[ng];
        int mg = m0 + ty * 4;
        // rows mg, mg+1 (pair 0)
        {
            float2 v0 = unpack2(acc[0][0]), v1 = unpack2(acc[0][1]);
            float2 v2 = unpack2(acc[0][2]), v3 = unpack2(acc[0][3]);
            float4 lo = make_float4(__expf(v0.x + bv.x), __expf(v1.x + bv.y),
                                    __expf(v2.x + bv.z), __expf(v3.x + bv.w));
            float4 hi = make_float4(__expf(v0.y + bv.x), __expf(v1.y + bv.y),
                                    __expf(v2.y + bv.z), __expf(v3.y + bv.w));
            *(float4*)&out[(size_t)mg * NUM_CITIES + ng] = lo;
            *(float4*)&out[(size_t)(mg + 1) * NUM_CITIES + ng] = hi;
            rs0 = lo.x + lo.y + lo.z + lo.w;
            rs1 = hi.x + hi.y + hi.z + hi.w;
        }
        // rows mg+2, mg+3 (pair 1)
        {
            float2 v0 = unpack2(acc[1][0]), v1 = unpack2(acc[1][1]);
            float2 v2 = unpack2(acc[1][2]), v3 = unpack2(acc[1][3]);
            float4 lo = make_float4(__expf(v0.x + bv.x), __expf(v1.x + bv.y),
                                    __expf(v2.x + bv.z), __expf(v3.x + bv.w));
            float4 hi = make_float4(__expf(v0.y + bv.x), __expf(v1.y + bv.y),
                                    __expf(v2.y + bv.z), __expf(v3.y + bv.w));
            *(float4*)&out[(size_t)(mg + 2) * NUM_CITIES + ng] = lo;
            *(float4*)&out[(size_t)(mg + 3) * NUM_CITIES + ng] = hi;
            rs2 = lo.x + lo.y + lo.z + lo.w;
            rs3 = hi.x + hi.y + hi.z + hi.w;
        }
    }

    // reduce across the 16 tx lanes (stays within each 16-lane half-warp)
#pragma unroll
    for (int o = 1; o < 16; o <<= 1) {
        rs0 += __shfl_xor_sync(0xffffffffu, rs0, o);
        rs1 += __shfl_xor_sync(0xffffffffu, rs1, o);
        rs2 += __shfl_xor_sync(0xffffffffu, rs2, o);
        rs3 += __shfl_xor_sync(0xffffffffu, rs3, o);
    }
    if (tx == 0) {
        int mg = m0 + ty * 4;
        g_partial[(size_t)(mg + 0) * NPB + blockIdx.x] = rs0;
        g_partial[(size_t)(mg + 1) * NPB + blockIdx.x] = rs1;
        g_partial[(size_t)(mg + 2) * NPB + blockIdx.x] = rs2;
        g_partial[(size_t)(mg + 3) * NPB + blockIdx.x] = rs3;
    }
}

// ---------------- K3: reduce per-block partials -> 1/rowsum -------------------
__global__ void __launch_bounds__(NT) rowreduce_kernel() {
    const int row = blockIdx.x;
    float s = 0.0f;
    for (int i = threadIdx.x; i < NPB; i += NT)
        s += g_partial[(size_t)row * NPB + i];
    __shared__ float red[NT];
    red[threadIdx.x] = s;
    __syncthreads();
    for (int o = NT / 2; o > 0; o >>= 1) {
        if (threadIdx.x < o) red[threadIdx.x] += red[threadIdx.x + o];
        __syncthreads();
    }
    if (threadIdx.x == 0) g_inv[row] = 1.0f / red[0];
}

// ---------------- K4: out *= 1/rowsum  (exp already applied in K2) ------------
__global__ void __launch_bounds__(NT) normalize_kernel(float* __restrict__ out)
{
    const int row = blockIdx.y;
    const int c = (blockIdx.x * NT + threadIdx.x) * 4;
    if (c < NUM_CITIES) {
        const float inv = g_inv[row];
        float4* p = (float4*)&out[(size_t)row * NUM_CITIES + c];
        float4 v = *p;
        v.x *= inv; v.y *= inv; v.z *= inv; v.w *= inv;
        *p = v;
    }
}

// ---------------- launch -------------------------------------------------------
extern "C" void kernel_launch(void* const* d_in, const int* in_sizes, int n_in,
                              void* d_out, int out_size)
{
    const int*   x    = (const int*)  d_in[0];   // [1024, 512]
    const float* emb  = (const float*)d_in[1];   // [50000, 50]
    const float* W_ih = (const float*)d_in[2];   // [256, 50]
    const float* W_hh = (const float*)d_in[3];   // [256, 64]
    const float* b_ih = (const float*)d_in[4];   // [256]
    const float* b_hh = (const float*)d_in[5];   // [256]
    const float* W_fc = (const float*)d_in[6];   // [50000, 64]
    const float* b_fc = (const float*)d_in[7];   // [50000]
    float* out = (float*)d_out;                  // [1024, 50000]

    pad_wih_kernel<<<G4, EMBP>>>(W_ih);
    transpose_wfc_kernel<<<dim3((NUM_CITIES + 31) / 32, HID / 32), dim3(32, 32)>>>(W_fc);
    lstm_kernel<<<BATCH / BR, NT>>>(x, emb, W_hh, b_ih, b_hh);
    logits_kernel<<<dim3(NPB, BATCH / 64), NT>>>(b_fc, out);
    rowreduce_kernel<<<BATCH, NT>>>();
    normalize_kernel<<<dim3((NUM_CITIES / 4 + NT - 1) / NT, BATCH), NT>>>(out);
}